// round 15
// baseline (speedup 1.0000x reference)
#include <cuda_runtime.h>

#define B 16
#define L 2048
#define EPS 1e-8f
#define ROWS_PER_BLK 16
#define THREADS 512

// Fused GAF: out[b][i][j] = s_i*s_j - r_i*r_j, s = clipped minmax scale of x
// (= cos(arccos(s))), r = sqrt(1-s^2) (= sin). No trig in the hot path — the
// angle-sum identity turns the L^2 kernel into 2 FMAs per output element,
// making the problem purely HBM-write-bound (256 MiB mandatory output).
//
// Shape fixed by measured sweep (rows/block {1,8,16,32}; 256/512 threads;
// persistent CTAs; STG.256; store hints): 16 rows/block, 512 threads,
// 16 STG.128 .cs stores/thread, 2 barriers/block with redundant per-warp
// min/max reduction. This round's single A/B: __launch_bounds__(512, 4)
// squeezes 34->32 regs so 4 blocks/SM fit the 64K regfile (occupancy
// limiter was registers by exactly 2 regs/thread).
__global__ void __launch_bounds__(THREADS, 4) gaf_fused_kernel(
    const float* __restrict__ x, float* __restrict__ out) {
    const int b  = blockIdx.y;
    const int i0 = blockIdx.x * ROWS_PER_BLK;
    const int t  = threadIdx.x;
    const int lane = t & 31;
    const int wid  = t >> 5;                 // 16 warps

    __shared__ float red_min[16], red_max[16];
    __shared__ float sh_si[ROWS_PER_BLK], sh_ri[ROWS_PER_BLK];

    // ---- load x row: 512 threads x float4 = 2048 elems ----
    const float4 v = reinterpret_cast<const float4*>(x + b * L)[t];

    float vmin = fminf(fminf(v.x, v.y), fminf(v.z, v.w));
    float vmax = fmaxf(fmaxf(v.x, v.y), fmaxf(v.z, v.w));
    #pragma unroll
    for (int o = 16; o > 0; o >>= 1) {
        vmin = fminf(vmin, __shfl_xor_sync(0xffffffffu, vmin, o));
        vmax = fmaxf(vmax, __shfl_xor_sync(0xffffffffu, vmax, o));
    }
    if (lane == 0) { red_min[wid] = vmin; red_max[wid] = vmax; }
    __syncthreads();

    // ---- every warp reduces the 16 partials itself (no broadcast barrier).
    //      Each lane seeds from a VALID partial; lanes 16-31 read duplicates
    //      of 0-15, and the {8,4,2,1} xor reduce (closed within each
    //      half-warp) converges all 32 lanes to the true min/max. ----
    float m0 = red_min[lane & 15];
    float m1 = red_max[lane & 15];
    #pragma unroll
    for (int o = 8; o > 0; o >>= 1) {
        m0 = fminf(m0, __shfl_xor_sync(0xffffffffu, m0, o));
        m1 = fmaxf(m1, __shfl_xor_sync(0xffffffffu, m1, o));
    }
    const float mn  = m0;
    const float inv = 2.0f / (m1 - m0 + EPS);

    // ---- own 4 j-values in registers ----
    float4 s4, r4;
    s4.x = fminf(fmaxf((v.x - mn) * inv - 1.0f, -1.0f + EPS), 1.0f - EPS);
    s4.y = fminf(fmaxf((v.y - mn) * inv - 1.0f, -1.0f + EPS), 1.0f - EPS);
    s4.z = fminf(fmaxf((v.z - mn) * inv - 1.0f, -1.0f + EPS), 1.0f - EPS);
    s4.w = fminf(fmaxf((v.w - mn) * inv - 1.0f, -1.0f + EPS), 1.0f - EPS);
    r4.x = sqrtf(fmaxf(1.0f - s4.x * s4.x, 0.0f));
    r4.y = sqrtf(fmaxf(1.0f - s4.y * s4.y, 0.0f));
    r4.z = sqrtf(fmaxf(1.0f - s4.z * s4.z, 0.0f));
    r4.w = sqrtf(fmaxf(1.0f - s4.w * s4.w, 0.0f));

    // ---- publish the 16 (si,ri) pairs this block needs ----
    // element i0+e is owned by thread (i0+e)>>2, component e&3
    const int rel = t * 4 - i0;
    if (rel >= 0 && rel < ROWS_PER_BLK) {
        sh_si[rel + 0] = s4.x;  sh_ri[rel + 0] = r4.x;
        sh_si[rel + 1] = s4.y;  sh_ri[rel + 1] = r4.y;
        sh_si[rel + 2] = s4.z;  sh_ri[rel + 2] = r4.z;
        sh_si[rel + 3] = s4.w;  sh_ri[rel + 3] = r4.w;
    }
    __syncthreads();

    float* base = out + (size_t)b * L * L + (size_t)i0 * L;

    // ---- 16 rows in two unrolled halves (bounds register pressure) ----
    #pragma unroll
    for (int h = 0; h < 2; h++) {
        float si[8], ri[8];
        #pragma unroll
        for (int k = 0; k < 8; k++) {
            si[k] = sh_si[h * 8 + k];
            ri[k] = sh_ri[h * 8 + k];
        }
        #pragma unroll
        for (int k = 0; k < 8; k++) {
            float4 o;
            o.x = si[k] * s4.x - ri[k] * r4.x;
            o.y = si[k] * s4.y - ri[k] * r4.y;
            o.z = si[k] * s4.z - ri[k] * r4.z;
            o.w = si[k] * s4.w - ri[k] * r4.w;
            __stcs(reinterpret_cast<float4*>(base + (size_t)(h * 8 + k) * L) + t, o);
        }
    }
}

extern "C" void kernel_launch(void* const* d_in, const int* in_sizes, int n_in,
                              void* d_out, int out_size) {
    const float* x = (const float*)d_in[0];
    float* out = (float*)d_out;

    dim3 grid(L / ROWS_PER_BLK, B);
    gaf_fused_kernel<<<grid, THREADS>>>(x, out);
}

// round 16
// speedup vs baseline: 1.0402x; 1.0402x over previous
#include <cuda_runtime.h>

#define B 16
#define L 2048
#define EPS 1e-8f
#define ROWS_PER_BLK 16
#define THREADS 512

// Fused GAF: out[b][i][j] = s_i*s_j - r_i*r_j, s = clipped minmax scale of x
// (= cos(arccos(s))), r = sqrt(1-s^2) (= sin). No trig in the hot path — the
// angle-sum identity turns the L^2 kernel into 2 FMAs per output element,
// making the problem purely HBM-write-bound (256 MiB mandatory output).
//
// FINAL FORM — every knob measured on GB300:
//   rows/block {1,8,16,32} -> 16;  threads {256,512} -> 512;
//   grid-2048 beats persistent CTAs;  STG.128 .cs (STG.256 cracked by ptxas,
//   default hint ties);  2 barriers/block via redundant per-warp min/max
//   reduce;  3 blocks/SM (forcing 4 via launch_bounds raised occupancy to
//   95% but REGRESSED: 4 interleaved store streams/SM degrade write
//   locality — occupancy != throughput at the bandwidth wall).
// Result: 34 regs, ~67% occ, kernel ~39.5-40.5us = ~6.8 TB/s effective
// store rate, ~85% of 8 TB/s HBM3e spec — at the machine write ceiling.
__global__ void __launch_bounds__(THREADS) gaf_fused_kernel(
    const float* __restrict__ x, float* __restrict__ out) {
    const int b  = blockIdx.y;
    const int i0 = blockIdx.x * ROWS_PER_BLK;
    const int t  = threadIdx.x;
    const int lane = t & 31;
    const int wid  = t >> 5;                 // 16 warps

    __shared__ float red_min[16], red_max[16];
    __shared__ float sh_si[ROWS_PER_BLK], sh_ri[ROWS_PER_BLK];

    // ---- load x row: 512 threads x float4 = 2048 elems ----
    const float4 v = reinterpret_cast<const float4*>(x + b * L)[t];

    float vmin = fminf(fminf(v.x, v.y), fminf(v.z, v.w));
    float vmax = fmaxf(fmaxf(v.x, v.y), fmaxf(v.z, v.w));
    #pragma unroll
    for (int o = 16; o > 0; o >>= 1) {
        vmin = fminf(vmin, __shfl_xor_sync(0xffffffffu, vmin, o));
        vmax = fmaxf(vmax, __shfl_xor_sync(0xffffffffu, vmax, o));
    }
    if (lane == 0) { red_min[wid] = vmin; red_max[wid] = vmax; }
    __syncthreads();

    // ---- every warp reduces the 16 partials itself (no broadcast barrier).
    //      Each lane seeds from a VALID partial; lanes 16-31 read duplicates
    //      of 0-15, and the {8,4,2,1} xor reduce (closed within each
    //      half-warp) converges all 32 lanes to the true min/max. ----
    float m0 = red_min[lane & 15];
    float m1 = red_max[lane & 15];
    #pragma unroll
    for (int o = 8; o > 0; o >>= 1) {
        m0 = fminf(m0, __shfl_xor_sync(0xffffffffu, m0, o));
        m1 = fmaxf(m1, __shfl_xor_sync(0xffffffffu, m1, o));
    }
    const float mn  = m0;
    const float inv = 2.0f / (m1 - m0 + EPS);

    // ---- own 4 j-values in registers ----
    float4 s4, r4;
    s4.x = fminf(fmaxf((v.x - mn) * inv - 1.0f, -1.0f + EPS), 1.0f - EPS);
    s4.y = fminf(fmaxf((v.y - mn) * inv - 1.0f, -1.0f + EPS), 1.0f - EPS);
    s4.z = fminf(fmaxf((v.z - mn) * inv - 1.0f, -1.0f + EPS), 1.0f - EPS);
    s4.w = fminf(fmaxf((v.w - mn) * inv - 1.0f, -1.0f + EPS), 1.0f - EPS);
    r4.x = sqrtf(fmaxf(1.0f - s4.x * s4.x, 0.0f));
    r4.y = sqrtf(fmaxf(1.0f - s4.y * s4.y, 0.0f));
    r4.z = sqrtf(fmaxf(1.0f - s4.z * s4.z, 0.0f));
    r4.w = sqrtf(fmaxf(1.0f - s4.w * s4.w, 0.0f));

    // ---- publish the 16 (si,ri) pairs this block needs ----
    // element i0+e is owned by thread (i0+e)>>2, component e&3
    const int rel = t * 4 - i0;
    if (rel >= 0 && rel < ROWS_PER_BLK) {
        sh_si[rel + 0] = s4.x;  sh_ri[rel + 0] = r4.x;
        sh_si[rel + 1] = s4.y;  sh_ri[rel + 1] = r4.y;
        sh_si[rel + 2] = s4.z;  sh_ri[rel + 2] = r4.z;
        sh_si[rel + 3] = s4.w;  sh_ri[rel + 3] = r4.w;
    }
    __syncthreads();

    float* base = out + (size_t)b * L * L + (size_t)i0 * L;

    // ---- 16 rows in two unrolled halves (bounds register pressure) ----
    #pragma unroll
    for (int h = 0; h < 2; h++) {
        float si[8], ri[8];
        #pragma unroll
        for (int k = 0; k < 8; k++) {
            si[k] = sh_si[h * 8 + k];
            ri[k] = sh_ri[h * 8 + k];
        }
        #pragma unroll
        for (int k = 0; k < 8; k++) {
            float4 o;
            o.x = si[k] * s4.x - ri[k] * r4.x;
            o.y = si[k] * s4.y - ri[k] * r4.y;
            o.z = si[k] * s4.z - ri[k] * r4.z;
            o.w = si[k] * s4.w - ri[k] * r4.w;
            __stcs(reinterpret_cast<float4*>(base + (size_t)(h * 8 + k) * L) + t, o);
        }
    }
}

extern "C" void kernel_launch(void* const* d_in, const int* in_sizes, int n_in,
                              void* d_out, int out_size) {
    const float* x = (const float*)d_in[0];
    float* out = (float*)d_out;

    dim3 grid(L / ROWS_PER_BLK, B);
    gaf_fused_kernel<<<grid, THREADS>>>(x, out);
}